// round 16
// baseline (speedup 1.0000x reference)
#include <cuda_runtime.h>
#include <cuda_bf16.h>
#include <cuda_fp16.h>
#include <math_constants.h>
#include <cstdint>

#define NTOK   4096
#define DMODEL 768
#define NH     12
#define HD     64
#define KSEL   16
#define MDB    32768
#define NCH    8
#define CHUNK  (MDB/NCH)   /* 4096 keys per chunk */
#define DFF    3072
#define NCAND  32          /* rescored candidates per token */

#define W_CPROJ_OFF 0
#define W_FC_OFF    (DMODEL*DMODEL)
#define W_PROJ_OFF  (DMODEL*DMODEL + DMODEL*DFF)
#define W_TOTAL     (DMODEL*DMODEL + 2*DMODEL*DFF)   /* 5308416 */

// ---------------- scratch (device globals; no allocation allowed) ----------
__device__ float g_ln   [NTOK*DMODEL];
__device__ float g_q    [NTOK*DMODEL];
__device__ float g_h    [NTOK*DMODEL];
__device__ __half g_attnh[NTOK*DMODEL];
__device__ __half g_lnh  [NTOK*DMODEL];
__device__ __half g_ff1h [NTOK*DFF];
__device__ __half g_wh   [W_TOTAL];          // fp16 weights (c_proj|fc|proj)
__device__ __nv_bfloat16 g_qb[NTOK*DMODEL];
__device__ __nv_bfloat16 g_kb[MDB*DMODEL];
__device__ uint32_t g_part[NTOK*NCH*KSEL];   // packed (ord16<<16 | 4095-lidx)

// ---------------- helpers ---------------------------------------------------
__device__ __forceinline__ uint32_t smem_u32(const void* p) {
    uint32_t a;
    asm("{ .reg .u64 t; cvta.to.shared.u64 t, %1; cvt.u32.u64 %0, t; }" : "=r"(a) : "l"(p));
    return a;
}

__device__ __forceinline__ void ldsm_x4(uint32_t& r0, uint32_t& r1,
                                        uint32_t& r2, uint32_t& r3, uint32_t addr) {
    asm volatile("ldmatrix.sync.aligned.m8n8.x4.shared.b16 {%0,%1,%2,%3}, [%4];"
                 : "=r"(r0), "=r"(r1), "=r"(r2), "=r"(r3) : "r"(addr));
}
__device__ __forceinline__ void ldsm_x4t(uint32_t& r0, uint32_t& r1,
                                         uint32_t& r2, uint32_t& r3, uint32_t addr) {
    asm volatile("ldmatrix.sync.aligned.m8n8.x4.trans.shared.b16 {%0,%1,%2,%3}, [%4];"
                 : "=r"(r0), "=r"(r1), "=r"(r2), "=r"(r3) : "r"(addr));
}

__device__ __forceinline__ void mma16816(float* c, const uint32_t* a, const uint32_t* b) {
    asm("mma.sync.aligned.m16n8k16.row.col.f32.bf16.bf16.f32 "
        "{%0,%1,%2,%3}, {%4,%5,%6,%7}, {%8,%9}, {%0,%1,%2,%3};"
        : "+f"(c[0]), "+f"(c[1]), "+f"(c[2]), "+f"(c[3])
        : "r"(a[0]), "r"(a[1]), "r"(a[2]), "r"(a[3]), "r"(b[0]), "r"(b[1]));
}
__device__ __forceinline__ void mma16816h(float* c, const uint32_t* a, const uint32_t* b) {
    asm("mma.sync.aligned.m16n8k16.row.col.f32.f16.f16.f32 "
        "{%0,%1,%2,%3}, {%4,%5,%6,%7}, {%8,%9}, {%0,%1,%2,%3};"
        : "+f"(c[0]), "+f"(c[1]), "+f"(c[2]), "+f"(c[3])
        : "r"(a[0]), "r"(a[1]), "r"(a[2]), "r"(a[3]), "r"(b[0]), "r"(b[1]));
}

// packed dual fp32 FMA (each lane exact rn fp32 FMA; bit-identical to FFMA)
__device__ __forceinline__ void fma_f32x2(unsigned long long& acc,
                                          unsigned long long a,
                                          unsigned long long b) {
    asm("fma.rn.f32x2 %0, %1, %2, %0;" : "+l"(acc) : "l"(a), "l"(b));
}
__device__ __forceinline__ unsigned long long dup_f32x2(float x) {
    unsigned long long r;
    uint32_t u = __float_as_uint(x);
    asm("mov.b64 %0, {%1, %1};" : "=l"(r) : "r"(u));
    return r;
}
__device__ __forceinline__ float2 unpack_f32x2(unsigned long long v) {
    uint32_t lo, hi;
    asm("mov.b64 {%0, %1}, %2;" : "=r"(lo), "=r"(hi) : "l"(v));
    return make_float2(__uint_as_float(lo), __uint_as_float(hi));
}

#define CP_ASYNC16(dst, src) \
    asm volatile("cp.async.cg.shared.global [%0], [%1], 16;" :: "r"(dst), "l"(src))
#define CP_COMMIT()  asm volatile("cp.async.commit_group;" ::: "memory")
#define CP_WAIT0()   asm volatile("cp.async.wait_group 0;" ::: "memory")

__device__ __forceinline__ float blockReduceSum(float v, float* red) {
    #pragma unroll
    for (int o = 16; o > 0; o >>= 1) v += __shfl_xor_sync(0xffffffffu, v, o);
    int w = threadIdx.x >> 5, l = threadIdx.x & 31;
    if (l == 0) red[w] = v;
    __syncthreads();
    if (w == 0) {
        float t = (l < 8) ? red[l] : 0.f;
        #pragma unroll
        for (int o = 4; o > 0; o >>= 1) t += __shfl_xor_sync(0xffffffffu, t, o);
        if (l == 0) red[0] = t;
    }
    __syncthreads();
    float r = red[0];
    __syncthreads();
    return r;
}

__device__ __forceinline__ float gelu_tanh(float x) {
    return 0.5f * x * (1.f + tanhf(0.7978845608028654f * (x + 0.044715f * x * x * x)));
}

__device__ __forceinline__ bool better(float s1, int i1, float s2, int i2) {
    return (s1 > s2) || (s1 == s2 && i1 < i2);
}

// bf16 order-preserving 16-bit key of a score
__device__ __forceinline__ uint32_t ord16(float s) {
    uint16_t b = __bfloat16_as_ushort(__float2bfloat16(s));
    uint16_t o = (b & 0x8000) ? (uint16_t)(~b) : (uint16_t)(b | 0x8000);
    return (uint32_t)o;
}
__device__ __forceinline__ uint32_t ord2(float a, float b) {
    return ord16(a) | (ord16(b) << 16);
}

__device__ __forceinline__ void ins16(uint32_t& val, uint32_t k, int lane) {
    unsigned gt = __ballot_sync(0xffffffffu, k > val);
    uint32_t up = __shfl_up_sync(0xffffffffu, val, 1);
    if (gt) {
        int p = __ffs(gt) - 1;
        if (lane > p && lane < 16) val = up;
        if (lane == p) val = k;
    }
}

// ---------------- layernorm: fp32 out (LN1) / fp16 out (LN2) ----------------
__global__ __launch_bounds__(256) void ln_kernel(
    const float* __restrict__ x, const float* __restrict__ g,
    const float* __restrict__ b, float* __restrict__ y)
{
    __shared__ float red[8];
    int row = blockIdx.x;
    const float* xr = x + (size_t)row * DMODEL;
    int t = threadIdx.x;
    float v0 = xr[t], v1 = xr[t + 256], v2 = xr[t + 512];
    float mu = blockReduceSum(v0 + v1 + v2, red) * (1.f / DMODEL);
    float d0 = v0 - mu, d1 = v1 - mu, d2 = v2 - mu;
    float var = blockReduceSum(d0 * d0 + d1 * d1 + d2 * d2, red) * (1.f / DMODEL);
    float rs = rsqrtf(var + 1e-5f);
    float* yr = y + (size_t)row * DMODEL;
    yr[t]       = d0 * rs * g[t]       + b[t];
    yr[t + 256] = d1 * rs * g[t + 256] + b[t + 256];
    yr[t + 512] = d2 * rs * g[t + 512] + b[t + 512];
}

__global__ __launch_bounds__(256) void lnh_kernel(
    const float* __restrict__ x, const float* __restrict__ g,
    const float* __restrict__ b, __half* __restrict__ y)
{
    __shared__ float red[8];
    int row = blockIdx.x;
    const float* xr = x + (size_t)row * DMODEL;
    int t = threadIdx.x;
    float v0 = xr[t], v1 = xr[t + 256], v2 = xr[t + 512];
    float mu = blockReduceSum(v0 + v1 + v2, red) * (1.f / DMODEL);
    float d0 = v0 - mu, d1 = v1 - mu, d2 = v2 - mu;
    float var = blockReduceSum(d0 * d0 + d1 * d1 + d2 * d2, red) * (1.f / DMODEL);
    float rs = rsqrtf(var + 1e-5f);
    __half* yr = y + (size_t)row * DMODEL;
    yr[t]       = __float2half_rn(d0 * rs * g[t]       + b[t]);
    yr[t + 256] = __float2half_rn(d1 * rs * g[t + 256] + b[t + 256]);
    yr[t + 512] = __float2half_rn(d2 * rs * g[t + 512] + b[t + 512]);
}

// ---------------- fp32 -> bf16 convert (dbk only; q folded into sgemm) ------
__global__ __launch_bounds__(256) void f2bf_kernel(
    const float* __restrict__ x, __nv_bfloat16* __restrict__ y)
{
    int i = blockIdx.x * 256 + threadIdx.x;
    float4 v = reinterpret_cast<const float4*>(x)[i];
    __nv_bfloat162 a = __floats2bfloat162_rn(v.x, v.y);
    __nv_bfloat162 b = __floats2bfloat162_rn(v.z, v.w);
    reinterpret_cast<__nv_bfloat162*>(y)[2 * i]     = a;
    reinterpret_cast<__nv_bfloat162*>(y)[2 * i + 1] = b;
}

// ---------------- convert value-path weights to fp16 -------------------------
__global__ __launch_bounds__(256) void w2h_kernel(
    const float* __restrict__ w1, const float* __restrict__ w2,
    const float* __restrict__ w3, __half* __restrict__ dst)
{
    int i = blockIdx.x * 256 + threadIdx.x;       // float4 index
    const int n1 = (DMODEL * DMODEL) / 4;
    const int n2 = (DMODEL * DFF) / 4;
    const float* src; int j;
    if (i < n1)           { src = w1; j = i; }
    else if (i < n1 + n2) { src = w2; j = i - n1; }
    else                  { src = w3; j = i - n1 - n2; }
    float4 v = reinterpret_cast<const float4*>(src)[j];
    __half2 a = __floats2half2_rn(v.x, v.y);
    __half2 b = __floats2half2_rn(v.z, v.w);
    reinterpret_cast<__half2*>(dst)[2 * i]     = a;
    reinterpret_cast<__half2*>(dst)[2 * i + 1] = b;
}

// ---------------- fp32 SGEMM, 64x128 tiles, 2-deep reg prefetch -------------
enum { EPI_BIAS = 0, EPI_BIAS_RES = 1, EPI_GELU = 2 };

template <int EPI>
__global__ __launch_bounds__(256) void sgemm_kernel(
    const float* __restrict__ A, int lda,
    const float* __restrict__ B, int ldb,
    const float* __restrict__ bias,
    const float* __restrict__ res,
    float* __restrict__ C, int ldc, int Kd,
    __nv_bfloat16* __restrict__ Cb)
{
    __shared__ float As[8][68];    // transposed: As[k][row], 64 rows
    __shared__ float Bs[8][132];
    int tid  = threadIdx.x;
    int brow = blockIdx.y * 64, bcol = blockIdx.x * 128;
    int arow = tid >> 1, acol = (tid & 1) * 4;       // tid<128 stages A
    int bkr  = tid >> 5, bcol4 = (tid & 31) * 4;
    const float* Ap = A + (size_t)(brow + arow) * lda + acol;
    const float* Bp = B + (size_t)bkr * ldb + bcol + bcol4;
    int rbase = (tid >> 4) * 4, cbase = (tid & 15) * 4;

    unsigned long long acc[4][4];
    #pragma unroll
    for (int i = 0; i < 4; i++)
        #pragma unroll
        for (int j = 0; j < 4; j++) acc[i][j] = 0ull;

    float4 av0, bv0, av1, bv1;
    if (tid < 128) av0 = *reinterpret_cast<const float4*>(Ap);
    bv0 = *reinterpret_cast<const float4*>(Bp);
    if (tid < 128) av1 = *reinterpret_cast<const float4*>(Ap + 8);
    bv1 = *reinterpret_cast<const float4*>(Bp + (size_t)8 * ldb);

    #define SG_PHASE(AV, BV, KNEXT)                                           \
        __syncthreads();                                                      \
        if (tid < 128) {                                                      \
            As[acol + 0][arow] = AV.x; As[acol + 1][arow] = AV.y;             \
            As[acol + 2][arow] = AV.z; As[acol + 3][arow] = AV.w;             \
        }                                                                     \
        *reinterpret_cast<float4*>(&Bs[bkr][bcol4]) = BV;                     \
        __syncthreads();                                                      \
        if ((KNEXT) < Kd) {                                                   \
            if (tid < 128) AV = *reinterpret_cast<const float4*>(Ap + (KNEXT)); \
            BV = *reinterpret_cast<const float4*>(Bp + (size_t)(KNEXT) * ldb); \
        }                                                                     \
        _Pragma("unroll")                                                     \
        for (int kk = 0; kk < 8; kk++) {                                      \
            float a[4];                                                       \
            *reinterpret_cast<float4*>(a) =                                   \
                *reinterpret_cast<const float4*>(&As[kk][rbase]);             \
            ulonglong2 b01 = *reinterpret_cast<const ulonglong2*>(&Bs[kk][cbase]);       \
            ulonglong2 b23 = *reinterpret_cast<const ulonglong2*>(&Bs[kk][cbase + 64]);  \
            _Pragma("unroll")                                                 \
            for (int i = 0; i < 4; i++) {                                     \
                unsigned long long ap = dup_f32x2(a[i]);                      \
                fma_f32x2(acc[i][0], ap, b01.x);                              \
                fma_f32x2(acc[i][1], ap, b01.y);                              \
                fma_f32x2(acc[i][2], ap, b23.x);                              \
                fma_f32x2(acc[i][3], ap, b23.y);                              \
            }                                                                 \
        }

    for (int k0 = 0; k0 < Kd; k0 += 16) {
        SG_PHASE(av0, bv0, k0 + 16)
        SG_PHASE(av1, bv1, k0 + 24)
    }
    #undef SG_PHASE

    #pragma unroll
    for (int i = 0; i < 4; i++) {
        int r = brow + rbase + i;
        #pragma unroll
        for (int jg = 0; jg < 2; jg++) {
            int c = bcol + cbase + jg * 64;
            float2 p0 = unpack_f32x2(acc[i][jg * 2 + 0]);
            float2 p1 = unpack_f32x2(acc[i][jg * 2 + 1]);
            float4 bi = *reinterpret_cast<const float4*>(bias + c);
            float4 v;
            v.x = p0.x + bi.x;
            v.y = p0.y + bi.y;
            v.z = p1.x + bi.z;
            v.w = p1.y + bi.w;
            if (EPI == EPI_BIAS_RES) {
                float4 rv = *reinterpret_cast<const float4*>(res + (size_t)r * ldc + c);
                v.x += rv.x; v.y += rv.y; v.z += rv.z; v.w += rv.w;
            } else if (EPI == EPI_GELU) {
                v.x = gelu_tanh(v.x); v.y = gelu_tanh(v.y);
                v.z = gelu_tanh(v.z); v.w = gelu_tanh(v.w);
            }
            *reinterpret_cast<float4*>(C + (size_t)r * ldc + c) = v;
            if (EPI == EPI_BIAS && Cb != nullptr) {
                __nv_bfloat162 h0 = __floats2bfloat162_rn(v.x, v.y);
                __nv_bfloat162 h1 = __floats2bfloat162_rn(v.z, v.w);
                __nv_bfloat162* qp =
                    reinterpret_cast<__nv_bfloat162*>(Cb + (size_t)r * ldc + c);
                qp[0] = h0; qp[1] = h1;
            }
        }
    }
}

// ---------------- fp16 tensor-core GEMM, cp.async pipelined -----------------
template <int EPI, typename CT, int TM>
__global__ __launch_bounds__(TM * 2, 512 / (TM * 2)) void hgemm_kernel(
    const __half* __restrict__ A, int lda,
    const __half* __restrict__ B, int ldb,
    const float* __restrict__ bias,
    const float* __restrict__ res,
    CT* __restrict__ C, int ldc, int Kd)
{
    constexpr int NT = TM * 2;
    constexpr int ABYTES = TM * 128;   // one A buffer (TM rows x 64 halfs)
    __shared__ __half Ash[2 * TM * 64];
    __shared__ __half Bsh[2 * 8192];   // [buf][64 rows][128] swizzled 256B rows
    uint32_t sA = smem_u32(Ash), sB = smem_u32(Bsh);
    int tid = threadIdx.x, lane = tid & 31, wid = tid >> 5;
    int warp_m = (TM == 128) ? (wid >> 2) : 0;
    int warp_n = (TM == 128) ? (wid & 3) : wid;
    int brow = blockIdx.y * TM, bcol = blockIdx.x * 128;

    float acc[4][4][4];
    #pragma unroll
    for (int mt = 0; mt < 4; mt++)
        #pragma unroll
        for (int nt = 0; nt < 4; nt++)
            #pragma unroll
            for (int r = 0; r < 4; r++) acc[mt][nt][r] = 0.f;

    auto stageA = [&](int kp, int buf) {
        #pragma unroll
        for (int it = 0; it < 4; it++) {          // TM*8 chunks over NT thr
            int id = tid + it * NT;
            int row = id >> 3, col = id & 7;
            uint32_t d = sA + buf * ABYTES + row * 128 + ((col ^ (row & 7)) << 4);
            const void* s = A + (size_t)(brow + row) * lda + kp + col * 8;
            CP_ASYNC16(d, s);
        }
    };
    auto stageB = [&](int kp, int buf) {
        #pragma unroll
        for (int it = 0; it < 1024 / NT; it++) {  // 1024 chunks
            int id = tid + it * NT;
            int k = id >> 4, c = id & 15;
            uint32_t d = sB + buf * 16384 + k * 256 + ((c ^ (k & 7)) << 4);
            const void* s = B + (size_t)(kp + k) * ldb + bcol + c * 8;
            CP_ASYNC16(d, s);
        }
    };

    uint32_t a_rel[4]; int a_rx[4];
    #pragma unroll
    for (int mt = 0; mt < 4; mt++) {
        int row = warp_m * 64 + mt * 16 + (lane & 15);
        a_rel[mt] = row * 128;
        a_rx[mt] = row & 7;
    }
    int a_ch = lane >> 4;

    uint32_t b_off[2];
    {
        int m_ = lane >> 3, r_ = lane & 7;
        int kl = (m_ & 1) * 8 + r_;
        #pragma unroll
        for (int g = 0; g < 2; g++) {
            int nchunk = warp_n * 4 + g * 2 + (m_ >> 1);
            b_off[g] = kl * 256 + ((nchunk ^ (kl & 7)) << 4);
        }
    }

    stageA(0, 0); stageB(0, 0); CP_COMMIT();

    int npan = Kd / 64;
    for (int p = 0; p < npan; p++) {
        CP_WAIT0();
        __syncthreads();
        if (p + 1 < npan) {
            stageA((p + 1) * 64, (p + 1) & 1);
            stageB((p + 1) * 64, (p + 1) & 1);
            CP_COMMIT();
        }
        uint32_t abase = sA + (p & 1) * ABYTES;
        uint32_t bbase = sB + (p & 1) * 16384;

        #pragma unroll
        for (int kk = 0; kk < 4; kk++) {
            uint32_t af[4][4], bf[2][4];
            #pragma unroll
            for (int mt = 0; mt < 4; mt++) {
                int ch = kk * 2 + a_ch;
                ldsm_x4(af[mt][0], af[mt][1], af[mt][2], af[mt][3],
                        abase + a_rel[mt] + ((ch ^ a_rx[mt]) << 4));
            }
            #pragma unroll
            for (int g = 0; g < 2; g++)
                ldsm_x4t(bf[g][0], bf[g][1], bf[g][2], bf[g][3],
                         bbase + kk * 4096 + b_off[g]);
            #pragma unroll
            for (int mt = 0; mt < 4; mt++) {
                mma16816h(acc[mt][0], af[mt], &bf[0][0]);
                mma16816h(acc[mt][1], af[mt], &bf[0][2]);
                mma16816h(acc[mt][2], af[mt], &bf[1][0]);
                mma16816h(acc[mt][3], af[mt], &bf[1][2]);
            }
        }
    }

    #pragma unroll
    for (int mt = 0; mt < 4; mt++) {
        #pragma unroll
        for (int rh = 0; rh < 2; rh++) {
            int r = brow + warp_m * 64 + mt * 16 + rh * 8 + (lane >> 2);
            #pragma unroll
            for (int nt = 0; nt < 4; nt++) {
                int c = bcol + warp_n * 32 + nt * 8 + 2 * (lane & 3);
                float vx = acc[mt][nt][rh * 2 + 0] + bias[c];
                float vy = acc[mt][nt][rh * 2 + 1] + bias[c + 1];
                if (EPI == EPI_BIAS_RES) {
                    float2 rv = *reinterpret_cast<const float2*>(res + (size_t)r * ldc + c);
                    vx += rv.x; vy += rv.y;
                } else if (EPI == EPI_GELU) {
                    vx = gelu_tanh(vx); vy = gelu_tanh(vy);
                }
                if (sizeof(CT) == 2) {
                    __half2 hv = __floats2half2_rn(vx, vy);
                    *reinterpret_cast<__half2*>((__half*)C + (size_t)r * ldc + c) = hv;
                } else {
                    *reinterpret_cast<float2*>((float*)C + (size_t)r * ldc + c) =
                        make_float2(vx, vy);
                }
            }
        }
    }
}

// ---------------- bf16 mma.sync score GEMM + register top-16 ----------------
// Sc: uint16 ord keys [128][136] (idx implied by column); smem 67584 B.
#define SC_SC 32768

__device__ __forceinline__ void stage64_async(
    uint32_t dstb, const __nv_bfloat16* __restrict__ src, int tid)
{
    #pragma unroll
    for (int it = 0; it < 4; it++) {
        int c = tid + it * 256;          // 1024 chunks = 128 rows x 8 x 16B
        int row = c >> 3, col = c & 7;
        uint32_t d = dstb + row * 128 + ((col ^ (row & 7)) << 4);
        const void* s = src + (size_t)row * DMODEL + col * 8;
        CP_ASYNC16(d, s);
    }
}

__global__ __launch_bounds__(256, 2) void score_topk_mma(
    const __nv_bfloat16* __restrict__ qb, const __nv_bfloat16* __restrict__ kb,
    uint32_t* __restrict__ part)
{
    extern __shared__ char dsm[];
    uint16_t (*Sc16)[136] = (uint16_t(*)[136])(dsm + SC_SC);
    uint32_t sbase = smem_u32(dsm);

    int tid = threadIdx.x, lane = tid & 31, wid = tid >> 5;
    int warp_m = wid >> 2, warp_n = wid & 3;
    int q0 = blockIdx.y * 128;
    int c0 = blockIdx.x * CHUNK;

    uint32_t lst[16];
    #pragma unroll
    for (int r = 0; r < 16; r++) lst[r] = (lane < 16) ? 0u : 0xffffffffu;

    uint32_t a_rel[4], b_rel[2];
    int a_rx[4], b_rx[2];
    #pragma unroll
    for (int mt = 0; mt < 4; mt++) {
        int row = warp_m * 64 + mt * 16 + (lane & 15);
        a_rel[mt] = row * 128;
        a_rx[mt] = row & 7;
    }
    #pragma unroll
    for (int pr = 0; pr < 2; pr++) {
        int row = warp_n * 32 + pr * 16 + (lane & 7) + ((lane >> 4) << 3);
        b_rel[pr] = row * 128;
        b_rx[pr] = row & 7;
    }
    int a_ch = lane >> 4;
    int b_ch = (lane >> 3) & 1;

    const __nv_bfloat16* qbase = qb + (size_t)q0 * DMODEL;

    stage64_async(sbase,         qbase, tid);
    stage64_async(sbase + 16384, kb + (size_t)c0 * DMODEL, tid);
    CP_COMMIT();

    for (int kt = 0; kt < CHUNK / 128; kt++) {
        int kb0 = c0 + kt * 128;
        const __nv_bfloat16* kbase = kb + (size_t)kb0 * DMODEL;

        float acc[4][4][4];
        #pragma unroll
        for (int mt = 0; mt < 4; mt++)
            #pragma unroll
            for (int nt = 0; nt < 4; nt++)
                #pragma unroll
                for (int r = 0; r < 4; r++) acc[mt][nt][r] = 0.f;

        for (int kc = 0; kc < DMODEL / 64; kc++) {
            CP_WAIT0();
            __syncthreads();
            if (kc + 1 < DMODEL / 64) {           // prefetch next slice
                uint32_t nb = sbase + ((kc + 1) & 1) * 32768;
                stage64_async(nb,         qbase + (kc + 1) * 64, tid);
                stage64_async(nb + 16384, kbase + (kc + 1) * 64, tid);
                CP_COMMIT();
            } else if (kt + 1 < CHUNK / 128) {    // last slice: prefetch next
                stage64_async(sbase,         qbase, tid);          // kt's slice0
                stage64_async(sbase + 16384,                       // into buf0
                              kb + (size_t)(kb0 + 128) * DMODEL, tid);
                CP_COMMIT();                      // buf0 dead here (kc=10 done)
            }
            uint32_t abase = sbase + (kc & 1) * 32768;
            uint32_t bbase = abase + 16384;

            #pragma unroll
            for (int kk = 0; kk < 4; kk++) {
                uint32_t af[4][4], bf[2][4];
                #pragma unroll
                for (int mt = 0; mt < 4; mt++) {
                    int ch = kk * 2 + a_ch;
                    ldsm_x4(af[mt][0], af[mt][1], af[mt][2], af[mt][3],
                            abase + a_rel[mt] + ((ch ^ a_rx[mt]) << 4));
                }
                #pragma unroll
                for (int pr = 0; pr < 2; pr++) {
                    int ch = kk * 2 + b_ch;
                    ldsm_x4(bf[pr][0], bf[pr][1], bf[pr][2], bf[pr][3],
                            bbase + b_rel[pr] + ((ch ^ b_rx[pr]) << 4));
                }
                #pragma unroll
                for (int mt = 0; mt < 4; mt++) {
                    mma16816(acc[mt][0], af[mt], &bf[0][0]);
                    mma16816(acc[mt][1], af[mt], &bf[0][2]);
                    mma16816(acc[mt][2], af[mt], &bf[1][0]);
                    mma16816(acc[mt][3], af[mt], &bf[1][2]);
                }
            }
        }

        // dump ord16 keys to Sc16 (clobbers buf1 region only)
        __syncthreads();
        #pragma unroll
        for (int mt = 0; mt < 4; mt++) {
            int r = warp_m * 64 + mt * 16 + (lane >> 2);
            #pragma unroll
            for (int nt = 0; nt < 4; nt++) {
                int c = warp_n * 32 + nt * 8 + 2 * (lane & 3);
                *reinterpret_cast<uint32_t*>(&Sc16[r][c]) =
                    ord2(acc[mt][nt][0], acc[mt][nt][1]);
                *reinterpret_cast<uint32_t*>(&Sc16[r + 8][c]) =
                    ord2(acc[mt][nt][2], acc[mt][nt][3]);
            }
        }
        __syncthreads();

        // scan: warp wid owns rows [wid*16, wid*16+16); keys rebuilt lazily
        #pragma unroll
        for (int r = 0; r < 16; r++) {
            int row = wid * 16 + r;
            uint2 v = *reinterpret_cast<const uint2*>(&Sc16[row][lane * 4]);
            uint32_t thr = __shfl_sync(0xffffffffu, lst[r], 15);
            uint32_t thrhi = thr >> 16;
            uint32_t mx2 = __vmaxu2(v.x, v.y);
            uint32_t mxo = max(mx2 & 0xffffu, mx2 >> 16);
            unsigned m = __ballot_sync(0xffffffffu, mxo >= thrhi);
            if (m) {
                int cl = kt * 128 + lane * 4;
                uint32_t kv0 = ((v.x & 0xffffu) << 16) | (uint32_t)(4095 - cl);
                uint32_t kv1 = (v.x & 0xffff0000u)     | (uint32_t)(4094 - cl);
                uint32_t kv2 = ((v.y & 0xffffu) << 16) | (uint32_t)(4093 - cl);
                uint32_t kv3 = (v.y & 0xffff0000u)     | (uint32_t)(4092 - cl);
                while (m) {
                    int src = __ffs(m) - 1; m &= m - 1;
                    uint32_t k0 = __shfl_sync(0xffffffffu, kv0, src);
                    uint32_t k1 = __shfl_sync(0xffffffffu, kv1, src);
                    uint32_t k2 = __shfl_sync(0xffffffffu, kv2, src);
                    uint32_t k3 = __shfl_sync(0xffffffffu, kv3, src);
                    thr = __shfl_sync(0xffffffffu, lst[r], 15);
                    if (k0 > thr) { ins16(lst[r], k0, lane); thr = __shfl_sync(0xffffffffu, lst[r], 15); }
                    if (k1 > thr) { ins16(lst[r], k1, lane); thr = __shfl_sync(0xffffffffu, lst[r], 15); }
                    if (k2 > thr) { ins16(lst[r], k2, lane); thr = __shfl_sync(0xffffffffu, lst[r], 15); }
                    if (k3 > thr) { ins16(lst[r], k3, lane); }
                }
            }
        }
        __syncthreads();   // scan done before next mainloop clobbers Sc16(buf1)
    }

    if (lane < 16) {
        #pragma unroll
        for (int r = 0; r < 16; r++) {
            int row = q0 + wid * 16 + r;
            part[((size_t)row * NCH + blockIdx.x) * KSEL + lane] = lst[r];
        }
    }
}

// ---------------- fused: merge -> exact rescore -> top-16 -> attention ------
// block = token, 384 threads (12 warps). Phase 0: warp 0 merges the 128
// packed per-chunk candidates to top-32 (identical reduce order to the old
// merge32_kernel). Phase 1-3 as before.
__global__ __launch_bounds__(384) void rescore_attn_kernel(
    const float* __restrict__ q, const float* __restrict__ dbk,
    const float* __restrict__ dbv, const uint32_t* __restrict__ part,
    __half* __restrict__ out)
{
    __shared__ float sq[DMODEL];
    __shared__ float ss[NCAND];
    __shared__ int   sid[NCAND];
    __shared__ int   sidx[KSEL];
    __shared__ float saw[NH][KSEL];
    int t = blockIdx.x, tid = threadIdx.x;
    int w = tid >> 5, lane = tid & 31;
    sq[tid]       = q[(size_t)t * DMODEL + tid];
    sq[tid + 384] = q[(size_t)t * DMODEL + tid + 384];

    // phase 0: warp 0 merges 128 packed candidates -> top-32 (verbatim logic)
    if (w == 0) {
        unsigned long long mk[4];
        #pragma unroll
        for (int j = 0; j < 4; j++) {
            int e = lane + 32 * j;
            uint32_t key = part[(size_t)t * 128 + e];
            int gid = (e >> 4) * CHUNK + 4095 - (int)(key & 0xfffu);
            mk[j] = ((unsigned long long)(key >> 16) << 32) |
                    (uint32_t)(0xffffffffu - gid);
        }
        for (int it = 0; it < NCAND; it++) {
            unsigned long long best = mk[0];
            #pragma unroll
            for (int j = 1; j < 4; j++) if (mk[j] > best) best = mk[j];
            #pragma unroll
            for (int o = 16; o > 0; o >>= 1) {
                unsigned long long ob = __shfl_xor_sync(0xffffffffu, best, o);
                if (ob > best) best = ob;
            }
            if (lane == 0)
                sid[it] = (int)(0xffffffffu - (uint32_t)best);
            #pragma unroll
            for (int j = 0; j < 4; j++) if (mk[j] == best) mk[j] = 0;
        }
    }
    __syncthreads();

    // phase 1: exact fp32 rescore (32 cands over 12 warps)
    for (int cc = w; cc < NCAND; cc += 12) {
        const float* kr = dbk + (size_t)sid[cc] * DMODEL;
        float p = 0.f;
        #pragma unroll
        for (int j = 0; j < DMODEL / 32; j++)
            p += sq[lane + 32 * j] * kr[lane + 32 * j];
        #pragma unroll
        for (int o = 16; o > 0; o >>= 1) p += __shfl_xor_sync(0xffffffffu, p, o);
        if (lane == 0) ss[cc] = p;
    }
    __syncthreads();

    // phase 2: warp 0 selects final top-16 (value desc, index asc)
    if (w == 0) {
        float s = ss[lane];
        int  id = sid[lane];
        for (int it = 0; it < KSEL; it++) {
            float bs = s; int bid = id;
            #pragma unroll
            for (int o = 16; o > 0; o >>= 1) {
                float os = __shfl_xor_sync(0xffffffffu, bs, o);
                int   oi = __shfl_xor_sync(0xffffffffu, bid, o);
                if (better(os, oi, bs, bid)) { bs = os; bid = oi; }
            }
            if (lane == 0) sidx[it] = bid;
            if (id == bid) { s = -CUDART_INF_F; id = 0x7fffffff; }
        }
    }
    __syncthreads();

    // phase 3: per-head softmax attention (warp = head)
    float q1 = sq[w * HD + lane], q2 = sq[w * HD + lane + 32];
    for (int m = 0; m < KSEL; m++) {
        const float* kr = dbk + (size_t)sidx[m] * DMODEL + w * HD;
        float p = q1 * kr[lane] + q2 * kr[lane + 32];
        #pragma unroll
        for (int o = 16; o > 0; o >>= 1) p += __shfl_xor_sync(0xffffffffu, p, o);
        if (lane == 0) saw[w][m] = p * 0.125f;
    }
    __syncwarp();
    {
        float x = (lane < KSEL) ? saw[w][lane] : -CUDART_INF_F;
        float mx = x;
        #pragma unroll
        for (int o = 16; o > 0; o >>= 1) mx = fmaxf(mx, __shfl_xor_sync(0xffffffffu, mx, o));
        float e = (lane < KSEL) ? expf(x - mx) : 0.f;
        float se = e;
        #pragma unroll
        for (int o = 16; o > 0; o >>= 1) se += __shfl_xor_sync(0xffffffffu, se, o);
        if (lane < KSEL) saw[w][lane] = e / se;
    }
    __syncwarp();
    float a1 = 0.f, a2 = 0.f;
    for (int m = 0; m < KSEL; m++) {
        float aw = saw[w][m];
        const float* vr = dbv + (size_t)sidx[m] * DMODEL + w * HD;
        a1 += aw * vr[lane]; a2 += aw * vr[lane + 32];
    }
    out[(size_t)t * DMODEL + w * HD + lane]      = __float2half_rn(a1);
    out[(size_t)t * DMODEL + w * HD + lane + 32] = __float2half_rn(a2);
}

// ---------------- launch (single stream) -------------------------------------
extern "C" void kernel_launch(void* const* d_in, const int* in_sizes, int n_in,
                              void* d_out, int out_size)
{
    const float* prev   = (const float*)d_in[0];
    const float* dbk    = (const float*)d_in[1];
    const float* dbv    = (const float*)d_in[2];
    const float* ln1g   = (const float*)d_in[3];
    const float* ln1b   = (const float*)d_in[4];
    const float* cattnw = (const float*)d_in[5];
    const float* cattnb = (const float*)d_in[6];
    const float* cprojw = (const float*)d_in[7];
    const float* cprojb = (const float*)d_in[8];
    const float* ln2g   = (const float*)d_in[9];
    const float* ln2b   = (const float*)d_in[10];
    const float* fcw    = (const float*)d_in[11];
    const float* fcb    = (const float*)d_in[12];
    const float* projw  = (const float*)d_in[13];
    const float* projb  = (const float*)d_in[14];
    float* out = (float*)d_out;

    float *p_ln, *p_q, *p_h;
    __half *p_attnh, *p_lnh, *p_ff1h, *p_wh;
    __nv_bfloat16 *p_qb, *p_kb;
    uint32_t *p_part;
    cudaGetSymbolAddress((void**)&p_ln,    g_ln);
    cudaGetSymbolAddress((void**)&p_q,     g_q);
    cudaGetSymbolAddress((void**)&p_h,     g_h);
    cudaGetSymbolAddress((void**)&p_attnh, g_attnh);
    cudaGetSymbolAddress((void**)&p_lnh,   g_lnh);
    cudaGetSymbolAddress((void**)&p_ff1h,  g_ff1h);
    cudaGetSymbolAddress((void**)&p_wh,    g_wh);
    cudaGetSymbolAddress((void**)&p_qb,    g_qb);
    cudaGetSymbolAddress((void**)&p_kb,    g_kb);
    cudaGetSymbolAddress((void**)&p_part,  g_part);

    const __half* cprojw_h = p_wh + W_CPROJ_OFF;
    const __half* fcw_h    = p_wh + W_FC_OFF;
    const __half* projw_h  = p_wh + W_PROJ_OFF;

    // 0. one-pass fp16 conversion of value-path weights
    w2h_kernel<<<(W_TOTAL / 4) / 256, 256>>>(cprojw, fcw, projw, p_wh);

    // 1. LN1 (exact fp32 — feeds selection-critical q path)
    ln_kernel<<<NTOK, 256>>>(prev, ln1g, ln1b, p_ln);

    // 2. q = LN1(x) @ c_attn_w[:, :768] + bias  (exact fp32; writes q + qb)
    sgemm_kernel<EPI_BIAS><<<dim3(DMODEL / 128, NTOK / 64), 256>>>(
        p_ln, DMODEL, cattnw, 3 * DMODEL, cattnb, nullptr, p_q, DMODEL, DMODEL,
        p_qb);

    // 3. bf16 conversion of db_keys
    f2bf_kernel<<<(MDB * DMODEL / 4) / 256, 256>>>(dbk, p_kb);

    // 4. bf16 mma.sync score GEMM + register top-16 (uint16 score tile)
    int smem = 32768 + 128 * 136 * 2;  // 67584 B
    cudaFuncSetAttribute(score_topk_mma,
                         cudaFuncAttributeMaxDynamicSharedMemorySize, smem);
    score_topk_mma<<<dim3(NCH, NTOK / 128), 256, smem>>>(p_qb, p_kb, p_part);

    // 5. fused merge -> exact rescore -> top-16 -> attention (fp16 out)
    rescore_attn_kernel<<<NTOK, 384>>>(p_q, dbk, dbv, p_part, p_attnh);

    // 6. h = attn @ c_proj_w + bias + residual  (fp16 TC, 64x128 tiles)
    hgemm_kernel<EPI_BIAS_RES, float, 64><<<dim3(DMODEL / 128, NTOK / 64), 128>>>(
        p_attnh, DMODEL, cprojw_h, DMODEL, cprojb, prev, p_h, DMODEL, DMODEL);

    // 7. LN2 (fp16 output — feeds fc GEMM only)
    lnh_kernel<<<NTOK, 256>>>(p_h, ln2g, ln2b, p_lnh);

    // 8. ff1 = gelu(LN2(h) @ fc_w + fc_b)       (fp16; 128x128 tiles)
    hgemm_kernel<EPI_GELU, __half, 128><<<dim3(DFF / 128, NTOK / 128), 256>>>(
        p_lnh, DMODEL, fcw_h, DFF, fcb, nullptr, p_ff1h, DFF, DMODEL);

    // 9. out = ff1 @ proj_w + proj_b + h        (fp16; 64x128 tiles)
    hgemm_kernel<EPI_BIAS_RES, float, 64><<<dim3(DMODEL / 128, NTOK / 64), 128>>>(
        p_ff1h, DFF, projw_h, DMODEL, projb, p_h, out, DMODEL, DFF);
}

// round 17
// speedup vs baseline: 1.0093x; 1.0093x over previous
#include <cuda_runtime.h>
#include <cuda_bf16.h>
#include <cuda_fp16.h>
#include <math_constants.h>
#include <cstdint>

#define NTOK   4096
#define DMODEL 768
#define NH     12
#define HD     64
#define KSEL   16
#define MDB    32768
#define NCH    8
#define CHUNK  (MDB/NCH)   /* 4096 keys per chunk */
#define DFF    3072
#define NCAND  32          /* rescored candidates per token */

#define W_CPROJ_OFF 0
#define W_FC_OFF    (DMODEL*DMODEL)
#define W_PROJ_OFF  (DMODEL*DMODEL + DMODEL*DFF)
#define W_TOTAL     (DMODEL*DMODEL + 2*DMODEL*DFF)   /* 5308416 */

// ---------------- scratch (device globals; no allocation allowed) ----------
__device__ float g_ln   [NTOK*DMODEL];
__device__ float g_q    [NTOK*DMODEL];
__device__ float g_h    [NTOK*DMODEL];
__device__ __half g_attnh[NTOK*DMODEL];
__device__ __half g_lnh  [NTOK*DMODEL];
__device__ __half g_ff1h [NTOK*DFF];
__device__ __half g_wh   [W_TOTAL];          // fp16 weights (c_proj|fc|proj)
__device__ __nv_bfloat16 g_qb[NTOK*DMODEL];
__device__ __nv_bfloat16 g_kb[MDB*DMODEL];
__device__ uint32_t g_part[NTOK*NCH*KSEL];   // packed (ord16<<16 | 4095-lidx)
__device__ int   g_cand  [NTOK*NCAND];

// ---------------- helpers ---------------------------------------------------
__device__ __forceinline__ uint32_t smem_u32(const void* p) {
    uint32_t a;
    asm("{ .reg .u64 t; cvta.to.shared.u64 t, %1; cvt.u32.u64 %0, t; }" : "=r"(a) : "l"(p));
    return a;
}

__device__ __forceinline__ void ldsm_x4(uint32_t& r0, uint32_t& r1,
                                        uint32_t& r2, uint32_t& r3, uint32_t addr) {
    asm volatile("ldmatrix.sync.aligned.m8n8.x4.shared.b16 {%0,%1,%2,%3}, [%4];"
                 : "=r"(r0), "=r"(r1), "=r"(r2), "=r"(r3) : "r"(addr));
}
__device__ __forceinline__ void ldsm_x4t(uint32_t& r0, uint32_t& r1,
                                         uint32_t& r2, uint32_t& r3, uint32_t addr) {
    asm volatile("ldmatrix.sync.aligned.m8n8.x4.trans.shared.b16 {%0,%1,%2,%3}, [%4];"
                 : "=r"(r0), "=r"(r1), "=r"(r2), "=r"(r3) : "r"(addr));
}

__device__ __forceinline__ void mma16816(float* c, const uint32_t* a, const uint32_t* b) {
    asm("mma.sync.aligned.m16n8k16.row.col.f32.bf16.bf16.f32 "
        "{%0,%1,%2,%3}, {%4,%5,%6,%7}, {%8,%9}, {%0,%1,%2,%3};"
        : "+f"(c[0]), "+f"(c[1]), "+f"(c[2]), "+f"(c[3])
        : "r"(a[0]), "r"(a[1]), "r"(a[2]), "r"(a[3]), "r"(b[0]), "r"(b[1]));
}
__device__ __forceinline__ void mma16816h(float* c, const uint32_t* a, const uint32_t* b) {
    asm("mma.sync.aligned.m16n8k16.row.col.f32.f16.f16.f32 "
        "{%0,%1,%2,%3}, {%4,%5,%6,%7}, {%8,%9}, {%0,%1,%2,%3};"
        : "+f"(c[0]), "+f"(c[1]), "+f"(c[2]), "+f"(c[3])
        : "r"(a[0]), "r"(a[1]), "r"(a[2]), "r"(a[3]), "r"(b[0]), "r"(b[1]));
}

// packed dual fp32 FMA (each lane exact rn fp32 FMA; bit-identical to FFMA)
__device__ __forceinline__ void fma_f32x2(unsigned long long& acc,
                                          unsigned long long a,
                                          unsigned long long b) {
    asm("fma.rn.f32x2 %0, %1, %2, %0;" : "+l"(acc) : "l"(a), "l"(b));
}
__device__ __forceinline__ unsigned long long dup_f32x2(float x) {
    unsigned long long r;
    uint32_t u = __float_as_uint(x);
    asm("mov.b64 %0, {%1, %1};" : "=l"(r) : "r"(u));
    return r;
}
__device__ __forceinline__ float2 unpack_f32x2(unsigned long long v) {
    uint32_t lo, hi;
    asm("mov.b64 {%0, %1}, %2;" : "=r"(lo), "=r"(hi) : "l"(v));
    return make_float2(__uint_as_float(lo), __uint_as_float(hi));
}

#define CP_ASYNC16(dst, src) \
    asm volatile("cp.async.cg.shared.global [%0], [%1], 16;" :: "r"(dst), "l"(src))
#define CP_COMMIT()  asm volatile("cp.async.commit_group;" ::: "memory")
#define CP_WAIT0()   asm volatile("cp.async.wait_group 0;" ::: "memory")

__device__ __forceinline__ float blockReduceSum(float v, float* red) {
    #pragma unroll
    for (int o = 16; o > 0; o >>= 1) v += __shfl_xor_sync(0xffffffffu, v, o);
    int w = threadIdx.x >> 5, l = threadIdx.x & 31;
    if (l == 0) red[w] = v;
    __syncthreads();
    if (w == 0) {
        float t = (l < 8) ? red[l] : 0.f;
        #pragma unroll
        for (int o = 4; o > 0; o >>= 1) t += __shfl_xor_sync(0xffffffffu, t, o);
        if (l == 0) red[0] = t;
    }
    __syncthreads();
    float r = red[0];
    __syncthreads();
    return r;
}

__device__ __forceinline__ float gelu_tanh(float x) {
    return 0.5f * x * (1.f + tanhf(0.7978845608028654f * (x + 0.044715f * x * x * x)));
}

__device__ __forceinline__ bool better(float s1, int i1, float s2, int i2) {
    return (s1 > s2) || (s1 == s2 && i1 < i2);
}

// bf16 order-preserving 16-bit key of a score
__device__ __forceinline__ uint32_t ord16(float s) {
    uint16_t b = __bfloat16_as_ushort(__float2bfloat16(s));
    uint16_t o = (b & 0x8000) ? (uint16_t)(~b) : (uint16_t)(b | 0x8000);
    return (uint32_t)o;
}
__device__ __forceinline__ uint32_t ord2(float a, float b) {
    return ord16(a) | (ord16(b) << 16);
}

__device__ __forceinline__ void ins16(uint32_t& val, uint32_t k, int lane) {
    unsigned gt = __ballot_sync(0xffffffffu, k > val);
    uint32_t up = __shfl_up_sync(0xffffffffu, val, 1);
    if (gt) {
        int p = __ffs(gt) - 1;
        if (lane > p && lane < 16) val = up;
        if (lane == p) val = k;
    }
}

// ---------------- layernorm: fp32 out (LN1) / fp16 out (LN2) ----------------
__global__ __launch_bounds__(256) void ln_kernel(
    const float* __restrict__ x, const float* __restrict__ g,
    const float* __restrict__ b, float* __restrict__ y)
{
    __shared__ float red[8];
    int row = blockIdx.x;
    const float* xr = x + (size_t)row * DMODEL;
    int t = threadIdx.x;
    float v0 = xr[t], v1 = xr[t + 256], v2 = xr[t + 512];
    float mu = blockReduceSum(v0 + v1 + v2, red) * (1.f / DMODEL);
    float d0 = v0 - mu, d1 = v1 - mu, d2 = v2 - mu;
    float var = blockReduceSum(d0 * d0 + d1 * d1 + d2 * d2, red) * (1.f / DMODEL);
    float rs = rsqrtf(var + 1e-5f);
    float* yr = y + (size_t)row * DMODEL;
    yr[t]       = d0 * rs * g[t]       + b[t];
    yr[t + 256] = d1 * rs * g[t + 256] + b[t + 256];
    yr[t + 512] = d2 * rs * g[t + 512] + b[t + 512];
}

__global__ __launch_bounds__(256) void lnh_kernel(
    const float* __restrict__ x, const float* __restrict__ g,
    const float* __restrict__ b, __half* __restrict__ y)
{
    __shared__ float red[8];
    int row = blockIdx.x;
    const float* xr = x + (size_t)row * DMODEL;
    int t = threadIdx.x;
    float v0 = xr[t], v1 = xr[t + 256], v2 = xr[t + 512];
    float mu = blockReduceSum(v0 + v1 + v2, red) * (1.f / DMODEL);
    float d0 = v0 - mu, d1 = v1 - mu, d2 = v2 - mu;
    float var = blockReduceSum(d0 * d0 + d1 * d1 + d2 * d2, red) * (1.f / DMODEL);
    float rs = rsqrtf(var + 1e-5f);
    __half* yr = y + (size_t)row * DMODEL;
    yr[t]       = __float2half_rn(d0 * rs * g[t]       + b[t]);
    yr[t + 256] = __float2half_rn(d1 * rs * g[t + 256] + b[t + 256]);
    yr[t + 512] = __float2half_rn(d2 * rs * g[t + 512] + b[t + 512]);
}

// ---------------- fp32 -> bf16 convert (dbk only; q folded into sgemm) ------
__global__ __launch_bounds__(256) void f2bf_kernel(
    const float* __restrict__ x, __nv_bfloat16* __restrict__ y)
{
    int i = blockIdx.x * 256 + threadIdx.x;
    float4 v = reinterpret_cast<const float4*>(x)[i];
    __nv_bfloat162 a = __floats2bfloat162_rn(v.x, v.y);
    __nv_bfloat162 b = __floats2bfloat162_rn(v.z, v.w);
    reinterpret_cast<__nv_bfloat162*>(y)[2 * i]     = a;
    reinterpret_cast<__nv_bfloat162*>(y)[2 * i + 1] = b;
}

// ---------------- convert value-path weights to fp16 -------------------------
__global__ __launch_bounds__(256) void w2h_kernel(
    const float* __restrict__ w1, const float* __restrict__ w2,
    const float* __restrict__ w3, __half* __restrict__ dst)
{
    int i = blockIdx.x * 256 + threadIdx.x;       // float4 index
    const int n1 = (DMODEL * DMODEL) / 4;
    const int n2 = (DMODEL * DFF) / 4;
    const float* src; int j;
    if (i < n1)           { src = w1; j = i; }
    else if (i < n1 + n2) { src = w2; j = i - n1; }
    else                  { src = w3; j = i - n1 - n2; }
    float4 v = reinterpret_cast<const float4*>(src)[j];
    __half2 a = __floats2half2_rn(v.x, v.y);
    __half2 b = __floats2half2_rn(v.z, v.w);
    reinterpret_cast<__half2*>(dst)[2 * i]     = a;
    reinterpret_cast<__half2*>(dst)[2 * i + 1] = b;
}

// ---------------- fp32 SGEMM, 64x128 tiles, 2-deep reg prefetch -------------
enum { EPI_BIAS = 0, EPI_BIAS_RES = 1, EPI_GELU = 2 };

template <int EPI>
__global__ __launch_bounds__(256) void sgemm_kernel(
    const float* __restrict__ A, int lda,
    const float* __restrict__ B, int ldb,
    const float* __restrict__ bias,
    const float* __restrict__ res,
    float* __restrict__ C, int ldc, int Kd,
    __nv_bfloat16* __restrict__ Cb)
{
    __shared__ float As[8][68];    // transposed: As[k][row], 64 rows
    __shared__ float Bs[8][132];
    int tid  = threadIdx.x;
    int brow = blockIdx.y * 64, bcol = blockIdx.x * 128;
    int arow = tid >> 1, acol = (tid & 1) * 4;       // tid<128 stages A
    int bkr  = tid >> 5, bcol4 = (tid & 31) * 4;
    const float* Ap = A + (size_t)(brow + arow) * lda + acol;
    const float* Bp = B + (size_t)bkr * ldb + bcol + bcol4;
    int rbase = (tid >> 4) * 4, cbase = (tid & 15) * 4;

    unsigned long long acc[4][4];
    #pragma unroll
    for (int i = 0; i < 4; i++)
        #pragma unroll
        for (int j = 0; j < 4; j++) acc[i][j] = 0ull;

    float4 av0, bv0, av1, bv1;
    if (tid < 128) av0 = *reinterpret_cast<const float4*>(Ap);
    bv0 = *reinterpret_cast<const float4*>(Bp);
    if (tid < 128) av1 = *reinterpret_cast<const float4*>(Ap + 8);
    bv1 = *reinterpret_cast<const float4*>(Bp + (size_t)8 * ldb);

    #define SG_PHASE(AV, BV, KNEXT)                                           \
        __syncthreads();                                                      \
        if (tid < 128) {                                                      \
            As[acol + 0][arow] = AV.x; As[acol + 1][arow] = AV.y;             \
            As[acol + 2][arow] = AV.z; As[acol + 3][arow] = AV.w;             \
        }                                                                     \
        *reinterpret_cast<float4*>(&Bs[bkr][bcol4]) = BV;                     \
        __syncthreads();                                                      \
        if ((KNEXT) < Kd) {                                                   \
            if (tid < 128) AV = *reinterpret_cast<const float4*>(Ap + (KNEXT)); \
            BV = *reinterpret_cast<const float4*>(Bp + (size_t)(KNEXT) * ldb); \
        }                                                                     \
        _Pragma("unroll")                                                     \
        for (int kk = 0; kk < 8; kk++) {                                      \
            float a[4];                                                       \
            *reinterpret_cast<float4*>(a) =                                   \
                *reinterpret_cast<const float4*>(&As[kk][rbase]);             \
            ulonglong2 b01 = *reinterpret_cast<const ulonglong2*>(&Bs[kk][cbase]);       \
            ulonglong2 b23 = *reinterpret_cast<const ulonglong2*>(&Bs[kk][cbase + 64]);  \
            _Pragma("unroll")                                                 \
            for (int i = 0; i < 4; i++) {                                     \
                unsigned long long ap = dup_f32x2(a[i]);                      \
                fma_f32x2(acc[i][0], ap, b01.x);                              \
                fma_f32x2(acc[i][1], ap, b01.y);                              \
                fma_f32x2(acc[i][2], ap, b23.x);                              \
                fma_f32x2(acc[i][3], ap, b23.y);                              \
            }                                                                 \
        }

    for (int k0 = 0; k0 < Kd; k0 += 16) {
        SG_PHASE(av0, bv0, k0 + 16)
        SG_PHASE(av1, bv1, k0 + 24)
    }
    #undef SG_PHASE

    #pragma unroll
    for (int i = 0; i < 4; i++) {
        int r = brow + rbase + i;
        #pragma unroll
        for (int jg = 0; jg < 2; jg++) {
            int c = bcol + cbase + jg * 64;
            float2 p0 = unpack_f32x2(acc[i][jg * 2 + 0]);
            float2 p1 = unpack_f32x2(acc[i][jg * 2 + 1]);
            float4 bi = *reinterpret_cast<const float4*>(bias + c);
            float4 v;
            v.x = p0.x + bi.x;
            v.y = p0.y + bi.y;
            v.z = p1.x + bi.z;
            v.w = p1.y + bi.w;
            if (EPI == EPI_BIAS_RES) {
                float4 rv = *reinterpret_cast<const float4*>(res + (size_t)r * ldc + c);
                v.x += rv.x; v.y += rv.y; v.z += rv.z; v.w += rv.w;
            } else if (EPI == EPI_GELU) {
                v.x = gelu_tanh(v.x); v.y = gelu_tanh(v.y);
                v.z = gelu_tanh(v.z); v.w = gelu_tanh(v.w);
            }
            *reinterpret_cast<float4*>(C + (size_t)r * ldc + c) = v;
            if (EPI == EPI_BIAS && Cb != nullptr) {
                __nv_bfloat162 h0 = __floats2bfloat162_rn(v.x, v.y);
                __nv_bfloat162 h1 = __floats2bfloat162_rn(v.z, v.w);
                __nv_bfloat162* qp =
                    reinterpret_cast<__nv_bfloat162*>(Cb + (size_t)r * ldc + c);
                qp[0] = h0; qp[1] = h1;
            }
        }
    }
}

// ---------------- fp16 tensor-core GEMM, cp.async pipelined -----------------
template <int EPI, typename CT, int TM>
__global__ __launch_bounds__(TM * 2, 512 / (TM * 2)) void hgemm_kernel(
    const __half* __restrict__ A, int lda,
    const __half* __restrict__ B, int ldb,
    const float* __restrict__ bias,
    const float* __restrict__ res,
    CT* __restrict__ C, int ldc, int Kd)
{
    constexpr int NT = TM * 2;
    constexpr int ABYTES = TM * 128;   // one A buffer (TM rows x 64 halfs)
    __shared__ __half Ash[2 * TM * 64];
    __shared__ __half Bsh[2 * 8192];   // [buf][64 rows][128] swizzled 256B rows
    uint32_t sA = smem_u32(Ash), sB = smem_u32(Bsh);
    int tid = threadIdx.x, lane = tid & 31, wid = tid >> 5;
    int warp_m = (TM == 128) ? (wid >> 2) : 0;
    int warp_n = (TM == 128) ? (wid & 3) : wid;
    int brow = blockIdx.y * TM, bcol = blockIdx.x * 128;

    float acc[4][4][4];
    #pragma unroll
    for (int mt = 0; mt < 4; mt++)
        #pragma unroll
        for (int nt = 0; nt < 4; nt++)
            #pragma unroll
            for (int r = 0; r < 4; r++) acc[mt][nt][r] = 0.f;

    auto stageA = [&](int kp, int buf) {
        #pragma unroll
        for (int it = 0; it < 4; it++) {          // TM*8 chunks over NT thr
            int id = tid + it * NT;
            int row = id >> 3, col = id & 7;
            uint32_t d = sA + buf * ABYTES + row * 128 + ((col ^ (row & 7)) << 4);
            const void* s = A + (size_t)(brow + row) * lda + kp + col * 8;
            CP_ASYNC16(d, s);
        }
    };
    auto stageB = [&](int kp, int buf) {
        #pragma unroll
        for (int it = 0; it < 1024 / NT; it++) {  // 1024 chunks
            int id = tid + it * NT;
            int k = id >> 4, c = id & 15;
            uint32_t d = sB + buf * 16384 + k * 256 + ((c ^ (k & 7)) << 4);
            const void* s = B + (size_t)(kp + k) * ldb + bcol + c * 8;
            CP_ASYNC16(d, s);
        }
    };

    uint32_t a_rel[4]; int a_rx[4];
    #pragma unroll
    for (int mt = 0; mt < 4; mt++) {
        int row = warp_m * 64 + mt * 16 + (lane & 15);
        a_rel[mt] = row * 128;
        a_rx[mt] = row & 7;
    }
    int a_ch = lane >> 4;

    uint32_t b_off[2];
    {
        int m_ = lane >> 3, r_ = lane & 7;
        int kl = (m_ & 1) * 8 + r_;
        #pragma unroll
        for (int g = 0; g < 2; g++) {
            int nchunk = warp_n * 4 + g * 2 + (m_ >> 1);
            b_off[g] = kl * 256 + ((nchunk ^ (kl & 7)) << 4);
        }
    }

    stageA(0, 0); stageB(0, 0); CP_COMMIT();

    int npan = Kd / 64;
    for (int p = 0; p < npan; p++) {
        CP_WAIT0();
        __syncthreads();
        if (p + 1 < npan) {
            stageA((p + 1) * 64, (p + 1) & 1);
            stageB((p + 1) * 64, (p + 1) & 1);
            CP_COMMIT();
        }
        uint32_t abase = sA + (p & 1) * ABYTES;
        uint32_t bbase = sB + (p & 1) * 16384;

        #pragma unroll
        for (int kk = 0; kk < 4; kk++) {
            uint32_t af[4][4], bf[2][4];
            #pragma unroll
            for (int mt = 0; mt < 4; mt++) {
                int ch = kk * 2 + a_ch;
                ldsm_x4(af[mt][0], af[mt][1], af[mt][2], af[mt][3],
                        abase + a_rel[mt] + ((ch ^ a_rx[mt]) << 4));
            }
            #pragma unroll
            for (int g = 0; g < 2; g++)
                ldsm_x4t(bf[g][0], bf[g][1], bf[g][2], bf[g][3],
                         bbase + kk * 4096 + b_off[g]);
            #pragma unroll
            for (int mt = 0; mt < 4; mt++) {
                mma16816h(acc[mt][0], af[mt], &bf[0][0]);
                mma16816h(acc[mt][1], af[mt], &bf[0][2]);
                mma16816h(acc[mt][2], af[mt], &bf[1][0]);
                mma16816h(acc[mt][3], af[mt], &bf[1][2]);
            }
        }
    }

    #pragma unroll
    for (int mt = 0; mt < 4; mt++) {
        #pragma unroll
        for (int rh = 0; rh < 2; rh++) {
            int r = brow + warp_m * 64 + mt * 16 + rh * 8 + (lane >> 2);
            #pragma unroll
            for (int nt = 0; nt < 4; nt++) {
                int c = bcol + warp_n * 32 + nt * 8 + 2 * (lane & 3);
                float vx = acc[mt][nt][rh * 2 + 0] + bias[c];
                float vy = acc[mt][nt][rh * 2 + 1] + bias[c + 1];
                if (EPI == EPI_BIAS_RES) {
                    float2 rv = *reinterpret_cast<const float2*>(res + (size_t)r * ldc + c);
                    vx += rv.x; vy += rv.y;
                } else if (EPI == EPI_GELU) {
                    vx = gelu_tanh(vx); vy = gelu_tanh(vy);
                }
                if (sizeof(CT) == 2) {
                    __half2 hv = __floats2half2_rn(vx, vy);
                    *reinterpret_cast<__half2*>((__half*)C + (size_t)r * ldc + c) = hv;
                } else {
                    *reinterpret_cast<float2*>((float*)C + (size_t)r * ldc + c) =
                        make_float2(vx, vy);
                }
            }
        }
    }
}

// ---------------- bf16 mma.sync score GEMM + register top-16 ----------------
// Sc: uint16 ord keys [128][136] (idx implied by column); smem 67584 B.
#define SC_SC 32768

__device__ __forceinline__ void stage64_async(
    uint32_t dstb, const __nv_bfloat16* __restrict__ src, int tid)
{
    #pragma unroll
    for (int it = 0; it < 4; it++) {
        int c = tid + it * 256;          // 1024 chunks = 128 rows x 8 x 16B
        int row = c >> 3, col = c & 7;
        uint32_t d = dstb + row * 128 + ((col ^ (row & 7)) << 4);
        const void* s = src + (size_t)row * DMODEL + col * 8;
        CP_ASYNC16(d, s);
    }
}

__global__ __launch_bounds__(256, 2) void score_topk_mma(
    const __nv_bfloat16* __restrict__ qb, const __nv_bfloat16* __restrict__ kb,
    uint32_t* __restrict__ part)
{
    extern __shared__ char dsm[];
    uint16_t (*Sc16)[136] = (uint16_t(*)[136])(dsm + SC_SC);
    uint32_t sbase = smem_u32(dsm);

    int tid = threadIdx.x, lane = tid & 31, wid = tid >> 5;
    int warp_m = wid >> 2, warp_n = wid & 3;
    int q0 = blockIdx.y * 128;
    int c0 = blockIdx.x * CHUNK;

    uint32_t lst[16];
    #pragma unroll
    for (int r = 0; r < 16; r++) lst[r] = (lane < 16) ? 0u : 0xffffffffu;

    uint32_t a_rel[4], b_rel[2];
    int a_rx[4], b_rx[2];
    #pragma unroll
    for (int mt = 0; mt < 4; mt++) {
        int row = warp_m * 64 + mt * 16 + (lane & 15);
        a_rel[mt] = row * 128;
        a_rx[mt] = row & 7;
    }
    #pragma unroll
    for (int pr = 0; pr < 2; pr++) {
        int row = warp_n * 32 + pr * 16 + (lane & 7) + ((lane >> 4) << 3);
        b_rel[pr] = row * 128;
        b_rx[pr] = row & 7;
    }
    int a_ch = lane >> 4;
    int b_ch = (lane >> 3) & 1;

    const __nv_bfloat16* qbase = qb + (size_t)q0 * DMODEL;

    stage64_async(sbase,         qbase, tid);
    stage64_async(sbase + 16384, kb + (size_t)c0 * DMODEL, tid);
    CP_COMMIT();

    for (int kt = 0; kt < CHUNK / 128; kt++) {
        int kb0 = c0 + kt * 128;
        const __nv_bfloat16* kbase = kb + (size_t)kb0 * DMODEL;

        float acc[4][4][4];
        #pragma unroll
        for (int mt = 0; mt < 4; mt++)
            #pragma unroll
            for (int nt = 0; nt < 4; nt++)
                #pragma unroll
                for (int r = 0; r < 4; r++) acc[mt][nt][r] = 0.f;

        for (int kc = 0; kc < DMODEL / 64; kc++) {
            CP_WAIT0();
            __syncthreads();
            if (kc + 1 < DMODEL / 64) {           // prefetch next slice
                uint32_t nb = sbase + ((kc + 1) & 1) * 32768;
                stage64_async(nb,         qbase + (kc + 1) * 64, tid);
                stage64_async(nb + 16384, kbase + (kc + 1) * 64, tid);
                CP_COMMIT();
            } else if (kt + 1 < CHUNK / 128) {    // last slice: prefetch next
                stage64_async(sbase,         qbase, tid);          // kt's slice0
                stage64_async(sbase + 16384,                       // into buf0
                              kb + (size_t)(kb0 + 128) * DMODEL, tid);
                CP_COMMIT();                      // buf0 dead here (kc=10 done)
            }
            uint32_t abase = sbase + (kc & 1) * 32768;
            uint32_t bbase = abase + 16384;

            #pragma unroll
            for (int kk = 0; kk < 4; kk++) {
                uint32_t af[4][4], bf[2][4];
                #pragma unroll
                for (int mt = 0; mt < 4; mt++) {
                    int ch = kk * 2 + a_ch;
                    ldsm_x4(af[mt][0], af[mt][1], af[mt][2], af[mt][3],
                            abase + a_rel[mt] + ((ch ^ a_rx[mt]) << 4));
                }
                #pragma unroll
                for (int pr = 0; pr < 2; pr++) {
                    int ch = kk * 2 + b_ch;
                    ldsm_x4(bf[pr][0], bf[pr][1], bf[pr][2], bf[pr][3],
                            bbase + b_rel[pr] + ((ch ^ b_rx[pr]) << 4));
                }
                #pragma unroll
                for (int mt = 0; mt < 4; mt++) {
                    mma16816(acc[mt][0], af[mt], &bf[0][0]);
                    mma16816(acc[mt][1], af[mt], &bf[0][2]);
                    mma16816(acc[mt][2], af[mt], &bf[1][0]);
                    mma16816(acc[mt][3], af[mt], &bf[1][2]);
                }
            }
        }

        // dump ord16 keys to Sc16 (clobbers buf1 region only)
        __syncthreads();
        #pragma unroll
        for (int mt = 0; mt < 4; mt++) {
            int r = warp_m * 64 + mt * 16 + (lane >> 2);
            #pragma unroll
            for (int nt = 0; nt < 4; nt++) {
                int c = warp_n * 32 + nt * 8 + 2 * (lane & 3);
                *reinterpret_cast<uint32_t*>(&Sc16[r][c]) =
                    ord2(acc[mt][nt][0], acc[mt][nt][1]);
                *reinterpret_cast<uint32_t*>(&Sc16[r + 8][c]) =
                    ord2(acc[mt][nt][2], acc[mt][nt][3]);
            }
        }
        __syncthreads();

        // scan: warp wid owns rows [wid*16, wid*16+16); keys rebuilt lazily
        #pragma unroll
        for (int r = 0; r < 16; r++) {
            int row = wid * 16 + r;
            uint2 v = *reinterpret_cast<const uint2*>(&Sc16[row][lane * 4]);
            uint32_t thr = __shfl_sync(0xffffffffu, lst[r], 15);
            uint32_t thrhi = thr >> 16;
            uint32_t mx2 = __vmaxu2(v.x, v.y);
            uint32_t mxo = max(mx2 & 0xffffu, mx2 >> 16);
            unsigned m = __ballot_sync(0xffffffffu, mxo >= thrhi);
            if (m) {
                int cl = kt * 128 + lane * 4;
                uint32_t kv0 = ((v.x & 0xffffu) << 16) | (uint32_t)(4095 - cl);
                uint32_t kv1 = (v.x & 0xffff0000u)     | (uint32_t)(4094 - cl);
                uint32_t kv2 = ((v.y & 0xffffu) << 16) | (uint32_t)(4093 - cl);
                uint32_t kv3 = (v.y & 0xffff0000u)     | (uint32_t)(4092 - cl);
                while (m) {
                    int src = __ffs(m) - 1; m &= m - 1;
                    uint32_t k0 = __shfl_sync(0xffffffffu, kv0, src);
                    uint32_t k1 = __shfl_sync(0xffffffffu, kv1, src);
                    uint32_t k2 = __shfl_sync(0xffffffffu, kv2, src);
                    uint32_t k3 = __shfl_sync(0xffffffffu, kv3, src);
                    thr = __shfl_sync(0xffffffffu, lst[r], 15);
                    if (k0 > thr) { ins16(lst[r], k0, lane); thr = __shfl_sync(0xffffffffu, lst[r], 15); }
                    if (k1 > thr) { ins16(lst[r], k1, lane); thr = __shfl_sync(0xffffffffu, lst[r], 15); }
                    if (k2 > thr) { ins16(lst[r], k2, lane); thr = __shfl_sync(0xffffffffu, lst[r], 15); }
                    if (k3 > thr) { ins16(lst[r], k3, lane); }
                }
            }
        }
        __syncthreads();   // scan done before next mainloop clobbers Sc16(buf1)
    }

    if (lane < 16) {
        #pragma unroll
        for (int r = 0; r < 16; r++) {
            int row = q0 + wid * 16 + r;
            part[((size_t)row * NCH + blockIdx.x) * KSEL + lane] = lst[r];
        }
    }
}

// ---------------- merge 128 packed candidates/row -> top-32 -----------------
__global__ __launch_bounds__(256) void merge32_kernel(
    const uint32_t* __restrict__ part, int* __restrict__ cand)
{
    int lane = threadIdx.x & 31;
    int row  = blockIdx.x * 8 + (threadIdx.x >> 5);
    unsigned long long mk[4];
    #pragma unroll
    for (int j = 0; j < 4; j++) {
        int e = lane + 32 * j;
        uint32_t key = part[(size_t)row * 128 + e];
        int gid = (e >> 4) * CHUNK + 4095 - (int)(key & 0xfffu);
        mk[j] = ((unsigned long long)(key >> 16) << 32) | (uint32_t)(0xffffffffu - gid);
    }
    for (int t = 0; t < NCAND; t++) {
        unsigned long long best = mk[0];
        #pragma unroll
        for (int j = 1; j < 4; j++) if (mk[j] > best) best = mk[j];
        #pragma unroll
        for (int o = 16; o > 0; o >>= 1) {
            unsigned long long ob = __shfl_xor_sync(0xffffffffu, best, o);
            if (ob > best) best = ob;
        }
        if (lane == 0)
            cand[row * NCAND + t] = (int)(0xffffffffu - (uint32_t)best);
        #pragma unroll
        for (int j = 0; j < 4; j++) if (mk[j] == best) mk[j] = 0;
    }
}

// ---------------- fused: exact fp32 rescore -> top-16 -> attention ----------
__global__ __launch_bounds__(384) void rescore_attn_kernel(
    const float* __restrict__ q, const float* __restrict__ dbk,
    const float* __restrict__ dbv, const int* __restrict__ cand,
    __half* __restrict__ out)
{
    __shared__ float sq[DMODEL];
    __shared__ float ss[NCAND];
    __shared__ int   sid[NCAND];
    __shared__ int   sidx[KSEL];
    __shared__ float saw[NH][KSEL];
    int t = blockIdx.x, tid = threadIdx.x;
    int w = tid >> 5, lane = tid & 31;
    sq[tid]       = q[(size_t)t * DMODEL + tid];
    sq[tid + 384] = q[(size_t)t * DMODEL + tid + 384];
    if (tid < NCAND) sid[tid] = cand[t * NCAND + tid];
    __syncthreads();

    for (int cc = w; cc < NCAND; cc += 12) {
        const float* kr = dbk + (size_t)sid[cc] * DMODEL;
        float p = 0.f;
        #pragma unroll
        for (int j = 0; j < DMODEL / 32; j++)
            p += sq[lane + 32 * j] * kr[lane + 32 * j];
        #pragma unroll
        for (int o = 16; o > 0; o >>= 1) p += __shfl_xor_sync(0xffffffffu, p, o);
        if (lane == 0) ss[cc] = p;
    }
    __syncthreads();

    if (w == 0) {
        float s = ss[lane];
        int  id = sid[lane];
        for (int it = 0; it < KSEL; it++) {
            float bs = s; int bid = id;
            #pragma unroll
            for (int o = 16; o > 0; o >>= 1) {
                float os = __shfl_xor_sync(0xffffffffu, bs, o);
                int   oi = __shfl_xor_sync(0xffffffffu, bid, o);
                if (better(os, oi, bs, bid)) { bs = os; bid = oi; }
            }
            if (lane == 0) sidx[it] = bid;
            if (id == bid) { s = -CUDART_INF_F; id = 0x7fffffff; }
        }
    }
    __syncthreads();

    float q1 = sq[w * HD + lane], q2 = sq[w * HD + lane + 32];
    for (int m = 0; m < KSEL; m++) {
        const float* kr = dbk + (size_t)sidx[m] * DMODEL + w * HD;
        float p = q1 * kr[lane] + q2 * kr[lane + 32];
        #pragma unroll
        for (int o = 16; o > 0; o >>= 1) p += __shfl_xor_sync(0xffffffffu, p, o);
        if (lane == 0) saw[w][m] = p * 0.125f;
    }
    __syncwarp();
    {
        float x = (lane < KSEL) ? saw[w][lane] : -CUDART_INF_F;
        float mx = x;
        #pragma unroll
        for (int o = 16; o > 0; o >>= 1) mx = fmaxf(mx, __shfl_xor_sync(0xffffffffu, mx, o));
        float e = (lane < KSEL) ? expf(x - mx) : 0.f;
        float se = e;
        #pragma unroll
        for (int o = 16; o > 0; o >>= 1) se += __shfl_xor_sync(0xffffffffu, se, o);
        if (lane < KSEL) saw[w][lane] = e / se;
    }
    __syncwarp();
    float a1 = 0.f, a2 = 0.f;
    for (int m = 0; m < KSEL; m++) {
        float aw = saw[w][m];
        const float* vr = dbv + (size_t)sidx[m] * DMODEL + w * HD;
        a1 += aw * vr[lane]; a2 += aw * vr[lane + 32];
    }
    out[(size_t)t * DMODEL + w * HD + lane]      = __float2half_rn(a1);
    out[(size_t)t * DMODEL + w * HD + lane + 32] = __float2half_rn(a2);
}

// ---------------- launch (single stream) -------------------------------------
extern "C" void kernel_launch(void* const* d_in, const int* in_sizes, int n_in,
                              void* d_out, int out_size)
{
    const float* prev   = (const float*)d_in[0];
    const float* dbk    = (const float*)d_in[1];
    const float* dbv    = (const float*)d_in[2];
    const float* ln1g   = (const float*)d_in[3];
    const float* ln1b   = (const float*)d_in[4];
    const float* cattnw = (const float*)d_in[5];
    const float* cattnb = (const float*)d_in[6];
    const float* cprojw = (const float*)d_in[7];
    const float* cprojb = (const float*)d_in[8];
    const float* ln2g   = (const float*)d_in[9];
    const float* ln2b   = (const float*)d_in[10];
    const float* fcw    = (const float*)d_in[11];
    const float* fcb    = (const float*)d_in[12];
    const float* projw  = (const float*)d_in[13];
    const float* projb  = (const float*)d_in[14];
    float* out = (float*)d_out;

    float *p_ln, *p_q, *p_h;
    __half *p_attnh, *p_lnh, *p_ff1h, *p_wh;
    __nv_bfloat16 *p_qb, *p_kb;
    uint32_t *p_part;
    int *p_cand;
    cudaGetSymbolAddress((void**)&p_ln,    g_ln);
    cudaGetSymbolAddress((void**)&p_q,     g_q);
    cudaGetSymbolAddress((void**)&p_h,     g_h);
    cudaGetSymbolAddress((void**)&p_attnh, g_attnh);
    cudaGetSymbolAddress((void**)&p_lnh,   g_lnh);
    cudaGetSymbolAddress((void**)&p_ff1h,  g_ff1h);
    cudaGetSymbolAddress((void**)&p_wh,    g_wh);
    cudaGetSymbolAddress((void**)&p_qb,    g_qb);
    cudaGetSymbolAddress((void**)&p_kb,    g_kb);
    cudaGetSymbolAddress((void**)&p_part,  g_part);
    cudaGetSymbolAddress((void**)&p_cand,  g_cand);

    const __half* cprojw_h = p_wh + W_CPROJ_OFF;
    const __half* fcw_h    = p_wh + W_FC_OFF;
    const __half* projw_h  = p_wh + W_PROJ_OFF;

    // 0. one-pass fp16 conversion of value-path weights
    w2h_kernel<<<(W_TOTAL / 4) / 256, 256>>>(cprojw, fcw, projw, p_wh);

    // 1. LN1 (exact fp32 — feeds selection-critical q path)
    ln_kernel<<<NTOK, 256>>>(prev, ln1g, ln1b, p_ln);

    // 2. q = LN1(x) @ c_attn_w[:, :768] + bias  (exact fp32; writes q + qb)
    sgemm_kernel<EPI_BIAS><<<dim3(DMODEL / 128, NTOK / 64), 256>>>(
        p_ln, DMODEL, cattnw, 3 * DMODEL, cattnb, nullptr, p_q, DMODEL, DMODEL,
        p_qb);

    // 3. bf16 conversion of db_keys
    f2bf_kernel<<<(MDB * DMODEL / 4) / 256, 256>>>(dbk, p_kb);

    // 4. bf16 mma.sync score GEMM + register top-16 (uint16 score tile)
    int smem = 32768 + 128 * 136 * 2;  // 67584 B
    cudaFuncSetAttribute(score_topk_mma,
                         cudaFuncAttributeMaxDynamicSharedMemorySize, smem);
    score_topk_mma<<<dim3(NCH, NTOK / 128), 256, smem>>>(p_qb, p_kb, p_part);

    // 5. merge 128 packed candidates -> top-32 per token
    merge32_kernel<<<NTOK / 8, 256>>>(p_part, p_cand);

    // 6. fused exact rescore -> top-16 -> per-head attention (fp16 out)
    rescore_attn_kernel<<<NTOK, 384>>>(p_q, dbk, dbv, p_cand, p_attnh);

    // 7. h = attn @ c_proj_w + bias + residual  (fp16 TC, 64x128 tiles)
    hgemm_kernel<EPI_BIAS_RES, float, 64><<<dim3(DMODEL / 128, NTOK / 64), 128>>>(
        p_attnh, DMODEL, cprojw_h, DMODEL, cprojb, prev, p_h, DMODEL, DMODEL);

    // 8. LN2 (fp16 output — feeds fc GEMM only)
    lnh_kernel<<<NTOK, 256>>>(p_h, ln2g, ln2b, p_lnh);

    // 9. ff1 = gelu(LN2(h) @ fc_w + fc_b)       (fp16; 128x128 tiles)
    hgemm_kernel<EPI_GELU, __half, 128><<<dim3(DFF / 128, NTOK / 128), 256>>>(
        p_lnh, DMODEL, fcw_h, DFF, fcb, nullptr, p_ff1h, DFF, DMODEL);

    // 10. out = ff1 @ proj_w + proj_b + h       (fp16; 64x128 tiles)
    hgemm_kernel<EPI_BIAS_RES, float, 64><<<dim3(DMODEL / 128, NTOK / 64), 128>>>(
        p_ff1h, DFF, projw_h, DMODEL, projb, p_h, out, DMODEL, DFF);
}